// round 1
// baseline (speedup 1.0000x reference)
#include <cuda_runtime.h>

#define NN   1024
#define BB   32

// Intermediate layer-1 output: (B, N, 6)
__device__ float g_h[BB * NN * 6];

// ---------------------------------------------------------------------------
// Layer 1: H=3, F=4, O=2.  grid (4 row-chunks, 3 heads, 32 batches), 256 thr.
// ---------------------------------------------------------------------------
__global__ void __launch_bounds__(256) gat1_kernel(
    const float* __restrict__ x,    // (B, N, 4)
    const float* __restrict__ W1,   // (3, 4, 2)
    const float* __restrict__ a1)   // (3, 4, 1)
{
    const int chunk = blockIdx.x;   // 0..3
    const int hd    = blockIdx.y;   // 0..2
    const int b     = blockIdx.z;   // 0..31
    const int tid   = threadIdx.x;

    __shared__ float4 sp[NN];       // (A, B, Wh0, Wh1)
    __shared__ float  ssrc[NN];
    __shared__ float  red[256];

    float w[8];
#pragma unroll
    for (int i = 0; i < 8; i++) w[i] = W1[hd * 8 + i];
    const float as0 = a1[hd * 4 + 0], as1 = a1[hd * 4 + 1];
    const float ad0 = a1[hd * 4 + 2], ad1 = a1[hd * 4 + 3];

    const float4* xb = reinterpret_cast<const float4*>(x) + b * NN;

    float lmax = -3.4e38f;
#pragma unroll
    for (int k = 0; k < 4; k++) {
        int j = tid + k * 256;
        float4 xv = xb[j];
        float wh0 = xv.x * w[0] + xv.y * w[2] + xv.z * w[4] + xv.w * w[6];
        float wh1 = xv.x * w[1] + xv.y * w[3] + xv.z * w[5] + xv.w * w[7];
        float ss = wh0 * as0 + wh1 * as1;
        float sd = wh0 * ad0 + wh1 * ad1;
        ssrc[j] = ss;
        sp[j] = make_float4(sd, 0.f, wh0, wh1);
        lmax = fmaxf(lmax, sd);
    }
    red[tid] = lmax;
    __syncthreads();
#pragma unroll
    for (int s = 128; s > 0; s >>= 1) {
        if (tid < s) red[tid] = fmaxf(red[tid], red[tid + s]);
        __syncthreads();
    }
    const float M = red[0];

    // Convert sd -> (A, B).  Each thread rewrites only its own slots.
#pragma unroll
    for (int k = 0; k < 4; k++) {
        int j = tid + k * 256;
        float4 v = sp[j];
        float sd = v.x;
        v.x = __expf(sd - M);
        v.y = __expf(0.2f * (sd - M));
        sp[j] = v;
    }
    __syncthreads();

    const int   i  = chunk * 256 + tid;
    const float ss = ssrc[i];
    const float u  = ss + M;
    const float m  = (u > 0.f) ? u : 0.2f * u;       // lrelu(u) = row max of e
    const float p  = __expf(u - m);
    const float q  = __expf(0.2f * u - m);
    const float thr = __expf(-u);                    // A_j > thr  <=>  t_ij > 0

    float denom = 0.f, n0 = 0.f, n1 = 0.f;
#pragma unroll 8
    for (int j = 0; j < NN; j++) {
        float4 v = sp[j];
        float wA = p * v.x;
        float wB = q * v.y;
        float wg = (v.x > thr) ? wA : wB;
        denom += wg;
        n0 = fmaf(wg, v.z, n0);
        n1 = fmaf(wg, v.w, n1);
    }
    float inv = 1.0f / denom;
    float o0 = n0 * inv, o1 = n1 * inv;
    o0 = (o0 > 0.f) ? o0 : expm1f(o0);
    o1 = (o1 > 0.f) ? o1 : expm1f(o1);

    float* dst = g_h + (b * NN + i) * 6 + hd * 2;
    dst[0] = o0;
    dst[1] = o1;
}

// ---------------------------------------------------------------------------
// Layer 2: H=1, F=6, O=4.  grid (4 row-chunks, 32 batches), 256 threads.
// ---------------------------------------------------------------------------
__global__ void __launch_bounds__(256) gat2_kernel(
    const float* __restrict__ W2,   // (1, 6, 4)
    const float* __restrict__ a2,   // (1, 8, 1)
    float* __restrict__ y)          // (B, N, 4)
{
    const int chunk = blockIdx.x;   // 0..3
    const int b     = blockIdx.y;   // 0..31
    const int tid   = threadIdx.x;

    __shared__ float4 sp[NN];       // (A, B, Wh0, Wh1)
    __shared__ float2 sq[NN];       // (Wh2, Wh3)
    __shared__ float  ssrc[NN];
    __shared__ float  red[256];

    float w[24];
#pragma unroll
    for (int i = 0; i < 24; i++) w[i] = W2[i];
    float asv[4], adv[4];
#pragma unroll
    for (int o = 0; o < 4; o++) { asv[o] = a2[o]; adv[o] = a2[4 + o]; }

    const float* hb = g_h + b * NN * 6;

    float lmax = -3.4e38f;
#pragma unroll
    for (int k = 0; k < 4; k++) {
        int j = tid + k * 256;
        const float2* hp = reinterpret_cast<const float2*>(hb + j * 6);
        float2 h0 = hp[0], h1 = hp[1], h2 = hp[2];
        float xf[6] = {h0.x, h0.y, h1.x, h1.y, h2.x, h2.y};
        float wh[4];
#pragma unroll
        for (int o = 0; o < 4; o++) {
            float acc = 0.f;
#pragma unroll
            for (int f = 0; f < 6; f++) acc = fmaf(xf[f], w[f * 4 + o], acc);
            wh[o] = acc;
        }
        float ss = 0.f, sd = 0.f;
#pragma unroll
        for (int o = 0; o < 4; o++) {
            ss = fmaf(wh[o], asv[o], ss);
            sd = fmaf(wh[o], adv[o], sd);
        }
        ssrc[j] = ss;
        sp[j] = make_float4(sd, 0.f, wh[0], wh[1]);
        sq[j] = make_float2(wh[2], wh[3]);
        lmax = fmaxf(lmax, sd);
    }
    red[tid] = lmax;
    __syncthreads();
#pragma unroll
    for (int s = 128; s > 0; s >>= 1) {
        if (tid < s) red[tid] = fmaxf(red[tid], red[tid + s]);
        __syncthreads();
    }
    const float M = red[0];

#pragma unroll
    for (int k = 0; k < 4; k++) {
        int j = tid + k * 256;
        float4 v = sp[j];
        float sd = v.x;
        v.x = __expf(sd - M);
        v.y = __expf(0.2f * (sd - M));
        sp[j] = v;
    }
    __syncthreads();

    const int   i  = chunk * 256 + tid;
    const float ss = ssrc[i];
    const float u  = ss + M;
    const float m  = (u > 0.f) ? u : 0.2f * u;
    const float p  = __expf(u - m);
    const float q  = __expf(0.2f * u - m);
    const float thr = __expf(-u);

    float denom = 0.f, n0 = 0.f, n1 = 0.f, n2 = 0.f, n3 = 0.f;
#pragma unroll 4
    for (int j = 0; j < NN; j++) {
        float4 v  = sp[j];
        float2 v2 = sq[j];
        float wg = (v.x > thr) ? p * v.x : q * v.y;
        denom += wg;
        n0 = fmaf(wg, v.z,  n0);
        n1 = fmaf(wg, v.w,  n1);
        n2 = fmaf(wg, v2.x, n2);
        n3 = fmaf(wg, v2.y, n3);
    }
    float inv = 1.0f / denom;
    float o0 = n0 * inv, o1 = n1 * inv, o2 = n2 * inv, o3 = n3 * inv;
    o0 = (o0 > 0.f) ? o0 : expm1f(o0);
    o1 = (o1 > 0.f) ? o1 : expm1f(o1);
    o2 = (o2 > 0.f) ? o2 : expm1f(o2);
    o3 = (o3 > 0.f) ? o3 : expm1f(o3);

    reinterpret_cast<float4*>(y)[b * NN + i] = make_float4(o0, o1, o2, o3);
}

extern "C" void kernel_launch(void* const* d_in, const int* in_sizes, int n_in,
                              void* d_out, int out_size)
{
    const float* x  = (const float*)d_in[0];
    const float* W1 = (const float*)d_in[1];
    const float* a1 = (const float*)d_in[2];
    const float* W2 = (const float*)d_in[3];
    const float* a2 = (const float*)d_in[4];
    float* y = (float*)d_out;

    dim3 g1(4, 3, BB);
    gat1_kernel<<<g1, 256>>>(x, W1, a1);

    dim3 g2(4, BB, 1);
    gat2_kernel<<<g2, 256>>>(W2, a2, y);
}

// round 2
// speedup vs baseline: 2.1456x; 2.1456x over previous
#include <cuda_runtime.h>

#define NN 1024
#define BB 32

// Intermediate layer-1 output: (B, N, 6)
__device__ float g_h[BB * NN * 6];

// ---- float <-> order-preserving uint ----
__device__ __forceinline__ unsigned encf(float f) {
    unsigned u = __float_as_uint(f);
    return (u & 0x80000000u) ? ~u : (u | 0x80000000u);
}
__device__ __forceinline__ float decf(unsigned u) {
    u = (u & 0x80000000u) ? (u & 0x7fffffffu) : ~u;
    return __uint_as_float(u);
}

// ---- inclusive block scan over 1024 elements (1 per thread), NA arrays ----
template<int NA>
__device__ __forceinline__ void blockScanIncl(float* v, float (*wsum)[32], int tid) {
    const int lane = tid & 31, wid = tid >> 5;
#pragma unroll
    for (int a = 0; a < NA; a++) {
#pragma unroll
        for (int d = 1; d < 32; d <<= 1) {
            float n = __shfl_up_sync(0xffffffffu, v[a], d);
            if (lane >= d) v[a] += n;
        }
        if (lane == 31) wsum[a][wid] = v[a];
    }
    __syncthreads();
    if (wid == 0) {
#pragma unroll
        for (int a = 0; a < NA; a++) {
            float w = wsum[a][lane];
#pragma unroll
            for (int d = 1; d < 32; d <<= 1) {
                float n = __shfl_up_sync(0xffffffffu, w, d);
                if (lane >= d) w += n;
            }
            wsum[a][lane] = w;
        }
    }
    __syncthreads();
    if (wid > 0) {
#pragma unroll
        for (int a = 0; a < NA; a++) v[a] += wsum[a][wid - 1];
    }
}

// ---- bitonic sort of 1024 u64 keys, 1024 threads; j<32 stages in registers ----
__device__ __forceinline__ void bitonicSort1024(unsigned long long* buf, int tid) {
    for (int k = 2; k <= NN; k <<= 1) {
        for (int j = k >> 1; j >= 32; j >>= 1) {
            __syncthreads();
            int ixj = tid ^ j;
            if (ixj > tid) {
                unsigned long long a = buf[tid], b = buf[ixj];
                bool asc = ((tid & k) == 0);
                if ((a > b) == asc) { buf[tid] = b; buf[ixj] = a; }
            }
        }
        __syncthreads();
        unsigned long long v = buf[tid];
        const bool asc = ((tid & k) == 0);
#pragma unroll
        for (int j = 16; j >= 1; j >>= 1) {
            if (j <= (k >> 1)) {
                unsigned long long o = __shfl_xor_sync(0xffffffffu, v, j);
                bool keepMin = (((tid & j) == 0) == asc);
                v = ((v <= o) == keepMin) ? v : o;
            }
        }
        buf[tid] = v;
        // next k-iteration's first op syncs before touching buf
    }
    __syncthreads();
}

// ---------------------------------------------------------------------------
// Layer 1: H=3, F=4, O=2.  One block per (head, batch). 1024 threads.
// ---------------------------------------------------------------------------
__global__ void __launch_bounds__(1024, 1) gat1_kernel(
    const float* __restrict__ x,    // (B, N, 4)
    const float* __restrict__ W1,   // (3, 4, 2)
    const float* __restrict__ a1)   // (3, 4, 1)
{
    __shared__ float2 swh[NN];                      // 8 KB
    __shared__ unsigned long long sortbuf[NN];      // 8 KB
    __shared__ float scan[6][NN];                   // 24 KB
    __shared__ float wsum[6][32];                   // 768 B   => ~41 KB

    const int hd  = blockIdx.x;
    const int b   = blockIdx.y;
    const int tid = threadIdx.x;

    float w[8];
#pragma unroll
    for (int i = 0; i < 8; i++) w[i] = W1[hd * 8 + i];
    const float as0 = a1[hd * 4 + 0], as1 = a1[hd * 4 + 1];
    const float ad0 = a1[hd * 4 + 2], ad1 = a1[hd * 4 + 3];

    // phase 0: per-node projection (node index = tid)
    float4 xv = reinterpret_cast<const float4*>(x)[b * NN + tid];
    float wh0 = xv.x * w[0] + xv.y * w[2] + xv.z * w[4] + xv.w * w[6];
    float wh1 = xv.x * w[1] + xv.y * w[3] + xv.z * w[5] + xv.w * w[7];
    float ss  = wh0 * as0 + wh1 * as1;     // kept in register (row i == tid)
    float sd  = wh0 * ad0 + wh1 * ad1;
    swh[tid] = make_float2(wh0, wh1);
    sortbuf[tid] = ((unsigned long long)encf(sd) << 32) | (unsigned)tid;

    bitonicSort1024(sortbuf, tid);

    const float M = decf((unsigned)(sortbuf[NN - 1] >> 32));

    // gather in sorted order, build scan inputs (B-group forward, A-group reversed)
    {
        unsigned long long key = sortbuf[tid];
        unsigned jj = (unsigned)key & 1023u;
        float sdj = decf((unsigned)(key >> 32));
        float A  = __expf(sdj - M);
        float Bv = __expf(0.2f * (sdj - M));
        float2 wh = swh[jj];
        scan[0][tid] = Bv;
        scan[1][tid] = Bv * wh.x;
        scan[2][tid] = Bv * wh.y;
        int rr = NN - 1 - tid;
        scan[3][rr] = A;
        scan[4][rr] = A * wh.x;
        scan[5][rr] = A * wh.y;
    }
    __syncthreads();

    float v[6];
#pragma unroll
    for (int a = 0; a < 6; a++) v[a] = scan[a][tid];
    blockScanIncl<6>(v, wsum, tid);
#pragma unroll
    for (int a = 0; a < 6; a++) scan[a][tid] = v[a];
    __syncthreads();

    // row phase: row i == tid
    const float u = ss + M;
    const float m = fmaxf(u, 0.2f * u);
    const float p = __expf(u - m);
    const float q = __expf(0.2f * u - m);
    const unsigned tgt = encf(-ss);

    const unsigned* kw = reinterpret_cast<const unsigned*>(sortbuf);
    int lo = 0, hi = NN;
    while (lo < hi) {
        int mid = (lo + hi) >> 1;
        if (kw[2 * mid + 1] > tgt) hi = mid; else lo = mid + 1;
    }
    float PB = 0.f, P0 = 0.f, P1 = 0.f, SA = 0.f, S0 = 0.f, S1 = 0.f;
    if (lo > 0)  { PB = scan[0][lo - 1]; P0 = scan[1][lo - 1]; P1 = scan[2][lo - 1]; }
    if (lo < NN) { int t2 = NN - 1 - lo; SA = scan[3][t2]; S0 = scan[4][t2]; S1 = scan[5][t2]; }

    float denom = q * PB + p * SA;
    float inv = 1.0f / denom;
    float o0 = (q * P0 + p * S0) * inv;
    float o1 = (q * P1 + p * S1) * inv;
    o0 = (o0 > 0.f) ? o0 : expm1f(o0);
    o1 = (o1 > 0.f) ? o1 : expm1f(o1);

    float* dst = g_h + (size_t)(b * NN + tid) * 6 + hd * 2;
    dst[0] = o0;
    dst[1] = o1;
}

// ---------------------------------------------------------------------------
// Layer 2: H=1, F=6, O=4.  One block per batch. 1024 threads.
// Two scan passes (B-group then A-group) to stay under 48 KB static smem.
// ---------------------------------------------------------------------------
__global__ void __launch_bounds__(1024, 1) gat2_kernel(
    const float* __restrict__ W2,   // (1, 6, 4)
    const float* __restrict__ a2,   // (1, 8, 1)
    float* __restrict__ y)          // (B, N, 4)
{
    __shared__ float4 swh[NN];                      // 16 KB
    __shared__ unsigned long long sortbuf[NN];      // 8 KB
    __shared__ float scan[5][NN];                   // 20 KB
    __shared__ float wsum[5][32];                   // 640 B  => ~44.6 KB

    const int b   = blockIdx.x;
    const int tid = threadIdx.x;

    float w[24];
#pragma unroll
    for (int i = 0; i < 24; i++) w[i] = W2[i];
    float asv[4], adv[4];
#pragma unroll
    for (int o = 0; o < 4; o++) { asv[o] = a2[o]; adv[o] = a2[4 + o]; }

    // phase 0
    const float* hb = g_h + (size_t)(b * NN + tid) * 6;
    float2 h0 = *reinterpret_cast<const float2*>(hb);
    float2 h1 = *reinterpret_cast<const float2*>(hb + 2);
    float2 h2 = *reinterpret_cast<const float2*>(hb + 4);
    float xf[6] = {h0.x, h0.y, h1.x, h1.y, h2.x, h2.y};
    float wh[4];
#pragma unroll
    for (int o = 0; o < 4; o++) {
        float acc = 0.f;
#pragma unroll
        for (int f = 0; f < 6; f++) acc = fmaf(xf[f], w[f * 4 + o], acc);
        wh[o] = acc;
    }
    float ss = 0.f, sd = 0.f;
#pragma unroll
    for (int o = 0; o < 4; o++) {
        ss = fmaf(wh[o], asv[o], ss);
        sd = fmaf(wh[o], adv[o], sd);
    }
    float4 whv = make_float4(wh[0], wh[1], wh[2], wh[3]);
    swh[tid] = whv;
    sortbuf[tid] = ((unsigned long long)encf(sd) << 32) | (unsigned)tid;

    bitonicSort1024(sortbuf, tid);

    const float M = decf((unsigned)(sortbuf[NN - 1] >> 32));

    // sorted-order gather (kept in registers for both passes)
    unsigned long long key = sortbuf[tid];
    unsigned jj = (unsigned)key & 1023u;
    float sdj = decf((unsigned)(key >> 32));
    float4 whs = swh[jj];

    // ---- pass B: forward prefix of B-group ----
    {
        float Bv = __expf(0.2f * (sdj - M));
        scan[0][tid] = Bv;
        scan[1][tid] = Bv * whs.x;
        scan[2][tid] = Bv * whs.y;
        scan[3][tid] = Bv * whs.z;
        scan[4][tid] = Bv * whs.w;
    }
    __syncthreads();
    float v[5];
#pragma unroll
    for (int a = 0; a < 5; a++) v[a] = scan[a][tid];
    blockScanIncl<5>(v, wsum, tid);
#pragma unroll
    for (int a = 0; a < 5; a++) scan[a][tid] = v[a];
    __syncthreads();

    // row part 1 (row i == tid): split point + prefix reads
    const float u = ss + M;
    const float m = fmaxf(u, 0.2f * u);
    const float p = __expf(u - m);
    const float q = __expf(0.2f * u - m);
    const unsigned tgt = encf(-ss);

    const unsigned* kw = reinterpret_cast<const unsigned*>(sortbuf);
    int lo = 0, hi = NN;
    while (lo < hi) {
        int mid = (lo + hi) >> 1;
        if (kw[2 * mid + 1] > tgt) hi = mid; else lo = mid + 1;
    }
    float PB = 0.f, P0 = 0.f, P1 = 0.f, P2 = 0.f, P3 = 0.f;
    if (lo > 0) {
        PB = scan[0][lo - 1]; P0 = scan[1][lo - 1]; P1 = scan[2][lo - 1];
        P2 = scan[3][lo - 1]; P3 = scan[4][lo - 1];
    }
    __syncthreads();   // all prefix reads done before overwrite

    // ---- pass A: suffix of A-group (stored reversed, forward-scanned) ----
    {
        float A = __expf(sdj - M);
        int rr = NN - 1 - tid;
        scan[0][rr] = A;
        scan[1][rr] = A * whs.x;
        scan[2][rr] = A * whs.y;
        scan[3][rr] = A * whs.z;
        scan[4][rr] = A * whs.w;
    }
    __syncthreads();
#pragma unroll
    for (int a = 0; a < 5; a++) v[a] = scan[a][tid];
    blockScanIncl<5>(v, wsum, tid);
#pragma unroll
    for (int a = 0; a < 5; a++) scan[a][tid] = v[a];
    __syncthreads();

    float SA = 0.f, S0 = 0.f, S1 = 0.f, S2 = 0.f, S3 = 0.f;
    if (lo < NN) {
        int t2 = NN - 1 - lo;
        SA = scan[0][t2]; S0 = scan[1][t2]; S1 = scan[2][t2];
        S2 = scan[3][t2]; S3 = scan[4][t2];
    }

    float denom = q * PB + p * SA;
    float inv = 1.0f / denom;
    float o0 = (q * P0 + p * S0) * inv;
    float o1 = (q * P1 + p * S1) * inv;
    float o2 = (q * P2 + p * S2) * inv;
    float o3 = (q * P3 + p * S3) * inv;
    o0 = (o0 > 0.f) ? o0 : expm1f(o0);
    o1 = (o1 > 0.f) ? o1 : expm1f(o1);
    o2 = (o2 > 0.f) ? o2 : expm1f(o2);
    o3 = (o3 > 0.f) ? o3 : expm1f(o3);

    reinterpret_cast<float4*>(y)[b * NN + tid] = make_float4(o0, o1, o2, o3);
}

extern "C" void kernel_launch(void* const* d_in, const int* in_sizes, int n_in,
                              void* d_out, int out_size)
{
    const float* x  = (const float*)d_in[0];
    const float* W1 = (const float*)d_in[1];
    const float* a1 = (const float*)d_in[2];
    const float* W2 = (const float*)d_in[3];
    const float* a2 = (const float*)d_in[4];
    float* y = (float*)d_out;

    gat1_kernel<<<dim3(3, BB), 1024>>>(x, W1, a1);
    gat2_kernel<<<BB, 1024>>>(W2, a2, y);
}